// round 1
// baseline (speedup 1.0000x reference)
#include <cuda_runtime.h>
#include <cuda_bf16.h>
#include <cstdint>

#define N_NODES 100000
#define N_EDGES 1600000
#define N_GRAPHS 64
#define D 128

#define SCAN_T 1024
#define NB ((N_NODES + SCAN_T - 1) / SCAN_T)   // 98

// ---------------- scratch (device globals; no allocation allowed) ----------
__device__ float g_h1[(size_t)N_NODES * D];
__device__ float g_h2[(size_t)N_NODES * D];
__device__ int   g_deg[N_NODES];
__device__ float g_dinv[N_NODES];
__device__ int   g_off[N_NODES + 1];
__device__ int   g_cur[N_NODES];
__device__ int   g_csr_src[N_EDGES];
__device__ float g_csr_w[N_EDGES];
__device__ int   g_bsum[NB];
__device__ int   g_boff[NB];
__device__ float g_pool[N_GRAPHS * D];
__device__ int   g_cnt[N_GRAPHS];
__device__ int   g_is64;

// ---------------- dtype detection (int32 vs int64 indices) -----------------
__global__ void k_detect(const void* ep) {
    if (threadIdx.x == 0) {
        const int* p = (const int*)ep;
        int is64 = 1;
        #pragma unroll
        for (int j = 0; j < 8; j++)
            if (p[2 * j + 1] != 0) is64 = 0;   // int64 little-endian high words == 0
        g_is64 = is64;
    }
}

__device__ __forceinline__ int load_idx(const void* p, long long i) {
    if (g_is64) return (int)((const long long*)p)[i];
    return ((const int*)p)[i];
}

// ---------------- zero scratch ----------------------------------------------
__global__ void k_zero() {
    int i = blockIdx.x * blockDim.x + threadIdx.x;
    if (i < N_NODES) g_deg[i] = 0;
    if (i < N_GRAPHS * D) g_pool[i] = 0.0f;
    if (i < N_GRAPHS) g_cnt[i] = 0;
}

// ---------------- degree count (in-degree over dst) -------------------------
__global__ void k_deg(const void* ep) {
    int e = blockIdx.x * blockDim.x + threadIdx.x;
    if (e >= N_EDGES) return;
    int d = load_idx(ep, (long long)N_EDGES + e);
    atomicAdd(&g_deg[d], 1);
}

__global__ void k_dinv() {
    int i = blockIdx.x * blockDim.x + threadIdx.x;
    if (i < N_NODES) g_dinv[i] = rsqrtf((float)g_deg[i] + 1.0f);  // +1 self loop
}

// ---------------- exclusive scan of degrees (3-phase) -----------------------
__global__ void k_scan1() {
    __shared__ int s[SCAN_T];
    int i = blockIdx.x * SCAN_T + threadIdx.x;
    int v = (i < N_NODES) ? g_deg[i] : 0;
    s[threadIdx.x] = v;
    __syncthreads();
    #pragma unroll
    for (int off = 1; off < SCAN_T; off <<= 1) {
        int t = (threadIdx.x >= off) ? s[threadIdx.x - off] : 0;
        __syncthreads();
        s[threadIdx.x] += t;
        __syncthreads();
    }
    if (i < N_NODES) g_off[i] = s[threadIdx.x] - v;     // exclusive within block
    if (threadIdx.x == SCAN_T - 1) g_bsum[blockIdx.x] = s[SCAN_T - 1];
}

__global__ void k_scan2() {
    if (threadIdx.x == 0) {
        int run = 0;
        for (int b = 0; b < NB; b++) { g_boff[b] = run; run += g_bsum[b]; }
        g_off[N_NODES] = run;                            // == N_EDGES
    }
}

__global__ void k_scan3() {
    int i = blockIdx.x * SCAN_T + threadIdx.x;
    if (i < N_NODES) {
        int v = g_off[i] + g_boff[blockIdx.x];
        g_off[i] = v;
        g_cur[i] = v;
    }
}

// ---------------- CSR scatter (counting sort by dst) ------------------------
__global__ void k_scatter(const void* ep) {
    int e = blockIdx.x * blockDim.x + threadIdx.x;
    if (e >= N_EDGES) return;
    int s = load_idx(ep, e);
    int d = load_idx(ep, (long long)N_EDGES + e);
    int pos = atomicAdd(&g_cur[d], 1);
    g_csr_src[pos] = s;
    g_csr_w[pos] = g_dinv[s] * g_dinv[d];
}

// ---------------- GEMM: Y[n,128] = X[n,128] @ W[128,128] --------------------
// 64 rows x 128 cols per block; 256 threads; thread: 8 rows x 4 cols.
#define GEMM_SMEM ((D * D + 64 * D) * 4)   // 96 KB
__global__ void __launch_bounds__(256) k_gemm(const float* __restrict__ X,
                                              const float* __restrict__ W,
                                              float* __restrict__ Y,
                                              int nrows) {
    extern __shared__ float sm[];
    float* sW = sm;              // [128][128]
    float* sX = sm + D * D;      // [64][128]
    const int tid = threadIdx.x;
    const int rowBase = blockIdx.x * 64;

    const float4* W4 = (const float4*)W;
    float4* sW4 = (float4*)sW;
    #pragma unroll
    for (int i = tid; i < D * (D / 4); i += 256) sW4[i] = W4[i];

    const float4* X4 = (const float4*)X;
    float4* sX4 = (float4*)sX;
    #pragma unroll
    for (int i = tid; i < 64 * (D / 4); i += 256) {
        int r = i >> 5;
        int row = rowBase + r;
        sX4[i] = (row < nrows) ? X4[(size_t)row * 32 + (i & 31)]
                               : make_float4(0.f, 0.f, 0.f, 0.f);
    }
    __syncthreads();

    const int c4 = tid & 31;     // col group: cols 4*c4 .. 4*c4+3
    const int r0 = tid >> 5;     // 0..7 ; rows r0, r0+8, ..., r0+56
    float4 acc[8];
    #pragma unroll
    for (int i = 0; i < 8; i++) acc[i] = make_float4(0.f, 0.f, 0.f, 0.f);

    #pragma unroll 2
    for (int k4 = 0; k4 < D / 4; k4++) {
        float4 xv[8];
        #pragma unroll
        for (int rr = 0; rr < 8; rr++)
            xv[rr] = *(const float4*)&sX[(r0 + rr * 8) * D + k4 * 4];
        #pragma unroll
        for (int kk = 0; kk < 4; kk++) {
            float4 w = *(const float4*)&sW[(k4 * 4 + kk) * D + c4 * 4];
            #pragma unroll
            for (int rr = 0; rr < 8; rr++) {
                float xs = (kk == 0) ? xv[rr].x : (kk == 1) ? xv[rr].y
                          : (kk == 2) ? xv[rr].z : xv[rr].w;
                acc[rr].x = fmaf(xs, w.x, acc[rr].x);
                acc[rr].y = fmaf(xs, w.y, acc[rr].y);
                acc[rr].z = fmaf(xs, w.z, acc[rr].z);
                acc[rr].w = fmaf(xs, w.w, acc[rr].w);
            }
        }
    }

    #pragma unroll
    for (int rr = 0; rr < 8; rr++) {
        int row = rowBase + r0 + rr * 8;
        if (row < nrows)
            *(float4*)&Y[(size_t)row * D + c4 * 4] = acc[rr];
    }
}

// ---------------- aggregation: out = relu( Ahat @ hin + bias ) --------------
// one warp per node; thread handles 4 contiguous features (float4).
__global__ void k_agg(const float* __restrict__ hin,
                      float* __restrict__ hout,
                      const float* __restrict__ bias) {
    int node = (blockIdx.x * blockDim.x + threadIdx.x) >> 5;
    if (node >= N_NODES) return;
    int lane = threadIdx.x & 31;

    const float4* h4 = (const float4*)hin;
    float dii = g_dinv[node];
    float sw = dii * dii;                       // self-loop weight
    float4 a = h4[(size_t)node * 32 + lane];
    float4 acc = make_float4(a.x * sw, a.y * sw, a.z * sw, a.w * sw);

    int beg = g_off[node];
    int end = g_off[node + 1];
    for (int e = beg; e < end; e++) {
        int s = g_csr_src[e];
        float wt = g_csr_w[e];
        float4 v = h4[(size_t)s * 32 + lane];
        acc.x = fmaf(v.x, wt, acc.x);
        acc.y = fmaf(v.y, wt, acc.y);
        acc.z = fmaf(v.z, wt, acc.z);
        acc.w = fmaf(v.w, wt, acc.w);
    }

    float4 b = ((const float4*)bias)[lane];
    acc.x = fmaxf(acc.x + b.x, 0.f);
    acc.y = fmaxf(acc.y + b.y, 0.f);
    acc.z = fmaxf(acc.z + b.z, 0.f);
    acc.w = fmaxf(acc.w + b.w, 0.f);
    ((float4*)hout)[(size_t)node * 32 + lane] = acc;
}

// ---------------- mean pool (batch is sorted: run-length + rare atomics) ----
#define NPB 128
__global__ void k_pool(const float* __restrict__ h, const void* batchp) {
    __shared__ int sg[NPB];
    int base = blockIdx.x * NPB;
    int t = threadIdx.x;                      // 128 threads == feature id
    int n_here = N_NODES - base;
    if (n_here > NPB) n_here = NPB;
    if (t < n_here) sg[t] = load_idx(batchp, base + t);
    __syncthreads();

    float acc = 0.f;
    int cur = sg[0];
    int runstart = 0;
    for (int n = 0; n < n_here; n++) {
        int g = sg[n];
        if (g != cur) {
            atomicAdd(&g_pool[cur * D + t], acc);
            if (t == 0) atomicAdd(&g_cnt[cur], n - runstart);
            acc = 0.f; cur = g; runstart = n;
        }
        acc += h[(size_t)(base + n) * D + t];
    }
    atomicAdd(&g_pool[cur * D + t], acc);
    if (t == 0) atomicAdd(&g_cnt[cur], n_here - runstart);
}

// ---------------- final FC: out = relu( (pool/cnt) @ Wfc + bfc ) ------------
__global__ void k_fc(const float* __restrict__ Wfc,
                     const float* __restrict__ bfc,
                     float* __restrict__ out) {
    __shared__ float srow[D];
    int g = blockIdx.x;
    int t = threadIdx.x;
    float cnt = fmaxf((float)g_cnt[g], 1.0f);
    srow[t] = g_pool[g * D + t] / cnt;
    __syncthreads();
    float acc = bfc[t];
    #pragma unroll 4
    for (int k = 0; k < D; k++)
        acc = fmaf(srow[k], Wfc[k * D + t], acc);
    out[g * D + t] = fmaxf(acc, 0.f);
}

// ---------------- launch ----------------------------------------------------
extern "C" void kernel_launch(void* const* d_in, const int* in_sizes, int n_in,
                              void* d_out, int out_size) {
    const float* x    = (const float*)d_in[0];
    const void*  edge = d_in[1];
    const void*  batch= d_in[2];
    const float* W1   = (const float*)d_in[3];
    const float* b1   = (const float*)d_in[4];
    const float* W2   = (const float*)d_in[5];
    const float* b2   = (const float*)d_in[6];
    const float* Wfc  = (const float*)d_in[7];
    const float* bfc  = (const float*)d_in[8];
    float* out = (float*)d_out;

    void *ph1 = nullptr, *ph2 = nullptr;
    cudaGetSymbolAddress(&ph1, g_h1);
    cudaGetSymbolAddress(&ph2, g_h2);
    float* h1 = (float*)ph1;
    float* h2 = (float*)ph2;

    cudaFuncSetAttribute(k_gemm, cudaFuncAttributeMaxDynamicSharedMemorySize,
                         GEMM_SMEM);

    const int EB = (N_EDGES + 255) / 256;
    const int NBlk = (N_NODES + 255) / 256;
    const int AGG_BLOCKS = (N_NODES * 32 + 255) / 256;   // 1 warp/node, 8 warps/block
    const int GEMM_GRID = (N_NODES + 63) / 64;

    // ---- graph preprocessing (runs every replay; ~50 us) ----
    k_zero<<<NBlk, 256>>>();
    k_detect<<<1, 32>>>(edge);
    k_deg<<<EB, 256>>>(edge);
    k_dinv<<<NBlk, 256>>>();
    k_scan1<<<NB, SCAN_T>>>();
    k_scan2<<<1, 32>>>();
    k_scan3<<<NB, SCAN_T>>>();
    k_scatter<<<EB, 256>>>(edge);

    // ---- layer 1 ----
    k_gemm<<<GEMM_GRID, 256, GEMM_SMEM>>>(x, W1, h1, N_NODES);
    k_agg<<<AGG_BLOCKS, 256>>>(h1, h2, b1);

    // ---- layer 2 ----
    k_gemm<<<GEMM_GRID, 256, GEMM_SMEM>>>(h2, W2, h1, N_NODES);
    k_agg<<<AGG_BLOCKS, 256>>>(h1, h2, b2);

    // ---- pool + fc ----
    k_pool<<<(N_NODES + NPB - 1) / NPB, NPB>>>(h2, batch);
    k_fc<<<N_GRAPHS, D>>>(Wfc, bfc, out);
}

// round 3
// speedup vs baseline: 1.1223x; 1.1223x over previous
#include <cuda_runtime.h>
#include <cuda_bf16.h>
#include <cstdint>

#define N_NODES 100000
#define N_EDGES 1600000
#define N_GRAPHS 64
#define D 128

#define SCAN_T 1024
#define NB ((N_NODES + SCAN_T - 1) / SCAN_T)   // 98

// ---------------- scratch (device globals; no allocation allowed) ----------
__device__ float g_h1[(size_t)N_NODES * D];
__device__ float g_h2[(size_t)N_NODES * D];
__device__ int   g_deg[N_NODES];
__device__ float g_dinv[N_NODES];
__device__ int   g_off[N_NODES + 1];
__device__ int   g_cur[N_NODES];
__device__ int   g_csr_src[N_EDGES];
__device__ float g_csr_w[N_EDGES];
__device__ int   g_bsum[NB];
__device__ float g_pool[N_GRAPHS * D];
__device__ int   g_cnt[N_GRAPHS];
__device__ int   g_is64;
__device__ float g_WT[2][D * D];     // W^T (fp32), built once per launch

// ---------------- helpers ---------------------------------------------------
__device__ __forceinline__ int load_idx(const void* p, long long i) {
    if (g_is64) return (int)((const long long*)p)[i];
    return ((const int*)p)[i];
}

// split fp32 into tf32 hi + residual (HW ignores low 13 bits of tf32 operand)
__device__ __forceinline__ void tf32split(float v, uint32_t& h, uint32_t& l) {
    h = __float_as_uint(v) & 0xFFFFE000u;
    l = __float_as_uint(v - __uint_as_float(h));
}

__device__ __forceinline__ void mma8(float* c, const uint32_t* a,
                                     const uint32_t* b) {
    asm volatile(
        "mma.sync.aligned.m16n8k8.row.col.f32.tf32.tf32.f32 "
        "{%0,%1,%2,%3}, {%4,%5,%6,%7}, {%8,%9}, {%0,%1,%2,%3};"
        : "+f"(c[0]), "+f"(c[1]), "+f"(c[2]), "+f"(c[3])
        : "r"(a[0]), "r"(a[1]), "r"(a[2]), "r"(a[3]), "r"(b[0]), "r"(b[1]));
}

// ---------------- init: zero scratch + detect dtype + transpose W -----------
__global__ void k_init(const void* ep, const float* W1, const float* W2) {
    int i = blockIdx.x * blockDim.x + threadIdx.x;
    if (i < N_NODES) g_deg[i] = 0;
    if (i < N_GRAPHS * D) g_pool[i] = 0.0f;
    if (i < N_GRAPHS) g_cnt[i] = 0;
    if (i == 0) {
        const int* p = (const int*)ep;
        int is64 = 1;
        #pragma unroll
        for (int j = 0; j < 8; j++)
            if (p[2 * j + 1] != 0) is64 = 0;
        g_is64 = is64;
        g_off[N_NODES] = N_EDGES;
    }
    if (i < 2 * D * D) {
        int m = i >> 14;            // 0 -> W1, 1 -> W2
        int j = i & (D * D - 1);
        int k = j >> 7, n = j & (D - 1);
        const float* W = m ? W2 : W1;
        g_WT[m][n * D + k] = W[k * D + n];   // W^T
    }
}

// ---------------- degree count (in-degree over dst) -------------------------
__global__ void k_deg(const void* ep) {
    int e = blockIdx.x * blockDim.x + threadIdx.x;
    if (e >= N_EDGES) return;
    int d = load_idx(ep, (long long)N_EDGES + e);
    atomicAdd(&g_deg[d], 1);
}

// ---------------- block-local exclusive scan + dinv --------------------------
__global__ void k_scan1() {
    __shared__ int s[SCAN_T];
    int i = blockIdx.x * SCAN_T + threadIdx.x;
    int v = (i < N_NODES) ? g_deg[i] : 0;
    if (i < N_NODES) g_dinv[i] = rsqrtf((float)v + 1.0f);  // +1 self loop
    s[threadIdx.x] = v;
    __syncthreads();
    #pragma unroll
    for (int off = 1; off < SCAN_T; off <<= 1) {
        int t = (threadIdx.x >= off) ? s[threadIdx.x - off] : 0;
        __syncthreads();
        s[threadIdx.x] += t;
        __syncthreads();
    }
    if (i < N_NODES) g_off[i] = s[threadIdx.x] - v;
    if (threadIdx.x == SCAN_T - 1) g_bsum[blockIdx.x] = s[SCAN_T - 1];
}

// ---------------- apply block offsets (block prefix computed in-kernel) -----
__global__ void k_scan3() {
    __shared__ int s_boff;
    int b = blockIdx.x;
    int t = threadIdx.x;
    if (t == 0) s_boff = 0;
    __syncthreads();
    int partial = 0;
    for (int j = t; j < b; j += SCAN_T) partial += g_bsum[j];
    if (partial) atomicAdd(&s_boff, partial);
    __syncthreads();
    int i = b * SCAN_T + t;
    if (i < N_NODES) {
        int v = g_off[i] + s_boff;
        g_off[i] = v;
        g_cur[i] = v;
    }
}

// ---------------- CSR scatter (counting sort by dst) ------------------------
__global__ void k_scatter(const void* ep) {
    int e = blockIdx.x * blockDim.x + threadIdx.x;
    if (e >= N_EDGES) return;
    int s = load_idx(ep, e);
    int d = load_idx(ep, (long long)N_EDGES + e);
    int pos = atomicAdd(&g_cur[d], 1);
    g_csr_src[pos] = s;
    g_csr_w[pos] = g_dinv[s] * g_dinv[d];
}

// ---------------- tensor-core GEMM via mma.sync tf32 (compensated) ----------
// Y[n,128] = X[n,128] @ W. CTA: 256 thr, 64 rows x 128 cols.
// Warp: 32 rows x 32 cols = 2 m-frags x 4 n-frags of m16n8k8.
// Smem: X tile fp32 [64][132], W^T fp32 [128][132] (pad 132 -> conflict-free).
#define XS 132
#define GEMM_SMEM ((64 * XS + 128 * XS) * 4)   // 101376 B

__global__ void __launch_bounds__(256) k_gemm_mma(const float* __restrict__ X,
                                                  const float* __restrict__ WT,
                                                  float* __restrict__ Y,
                                                  int nrows) {
    extern __shared__ float sm[];
    float* sX = sm;               // [64][132]
    float* sW = sm + 64 * XS;     // [128][132]  (W^T: [n][k])

    const int tid = threadIdx.x;
    const int rowBase = blockIdx.x * 64;

    const float4* X4 = (const float4*)X;
    const float4* WT4 = (const float4*)WT;
    #pragma unroll
    for (int i = tid; i < 64 * 32; i += 256) {
        int r = i >> 5, c = i & 31;
        float4 v = make_float4(0.f, 0.f, 0.f, 0.f);
        if (rowBase + r < nrows) v = X4[(size_t)(rowBase + r) * 32 + c];
        *(float4*)&sX[r * XS + c * 4] = v;
    }
    #pragma unroll
    for (int i = tid; i < 128 * 32; i += 256) {
        int r = i >> 5, c = i & 31;
        *(float4*)&sW[r * XS + c * 4] = WT4[r * 32 + c];
    }
    __syncthreads();

    const int wid = tid >> 5, lane = tid & 31;
    const int g = lane >> 2, tg = lane & 3;
    const int mbase = (wid >> 2) * 32;   // 0 or 32
    const int nbase = (wid & 3) * 32;    // 0,32,64,96

    float acc[2][4][4];
    #pragma unroll
    for (int mf = 0; mf < 2; mf++)
        #pragma unroll
        for (int nf = 0; nf < 4; nf++)
            #pragma unroll
            for (int j = 0; j < 4; j++) acc[mf][nf][j] = 0.f;

    #pragma unroll 4
    for (int kc = 0; kc < 16; kc++) {
        const int k0 = kc * 8 + tg;

        uint32_t ah[2][4], al[2][4];
        #pragma unroll
        for (int mf = 0; mf < 2; mf++) {
            int r = mbase + mf * 16 + g;
            float v0 = sX[r * XS + k0];
            float v1 = sX[(r + 8) * XS + k0];
            float v2 = sX[r * XS + k0 + 4];
            float v3 = sX[(r + 8) * XS + k0 + 4];
            tf32split(v0, ah[mf][0], al[mf][0]);
            tf32split(v1, ah[mf][1], al[mf][1]);
            tf32split(v2, ah[mf][2], al[mf][2]);
            tf32split(v3, ah[mf][3], al[mf][3]);
        }

        uint32_t bh[4][2], bl[4][2];
        #pragma unroll
        for (int nf = 0; nf < 4; nf++) {
            int n = nbase + nf * 8 + g;
            float v0 = sW[n * XS + k0];
            float v1 = sW[n * XS + k0 + 4];
            tf32split(v0, bh[nf][0], bl[nf][0]);
            tf32split(v1, bh[nf][1], bl[nf][1]);
        }

        #pragma unroll
        for (int mf = 0; mf < 2; mf++)
            #pragma unroll
            for (int nf = 0; nf < 4; nf++) {
                mma8(acc[mf][nf], ah[mf], bh[nf]);
                mma8(acc[mf][nf], ah[mf], bl[nf]);
                mma8(acc[mf][nf], al[mf], bh[nf]);
            }
    }

    // epilogue: c0,c1 -> (row, col..col+1); c2,c3 -> (row+8, ...)
    #pragma unroll
    for (int mf = 0; mf < 2; mf++) {
        int row = rowBase + mbase + mf * 16 + g;
        #pragma unroll
        for (int nf = 0; nf < 4; nf++) {
            int col = nbase + nf * 8 + 2 * tg;
            if (row < nrows)
                *(float2*)&Y[(size_t)row * D + col] =
                    make_float2(acc[mf][nf][0], acc[mf][nf][1]);
            if (row + 8 < nrows)
                *(float2*)&Y[(size_t)(row + 8) * D + col] =
                    make_float2(acc[mf][nf][2], acc[mf][nf][3]);
        }
    }
}

// ---------------- aggregation: out = relu( Ahat @ hin + bias ) --------------
__global__ void k_agg(const float* __restrict__ hin,
                      float* __restrict__ hout,
                      const float* __restrict__ bias) {
    int node = (blockIdx.x * blockDim.x + threadIdx.x) >> 5;
    if (node >= N_NODES) return;
    int lane = threadIdx.x & 31;

    const float4* h4 = (const float4*)hin;
    float dii = g_dinv[node];
    float sw = dii * dii;
    float4 a = h4[(size_t)node * 32 + lane];
    float4 acc = make_float4(a.x * sw, a.y * sw, a.z * sw, a.w * sw);

    int beg = g_off[node];
    int end = g_off[node + 1];
    for (int e = beg; e < end; e++) {
        int s = g_csr_src[e];
        float wt = g_csr_w[e];
        float4 v = h4[(size_t)s * 32 + lane];
        acc.x = fmaf(v.x, wt, acc.x);
        acc.y = fmaf(v.y, wt, acc.y);
        acc.z = fmaf(v.z, wt, acc.z);
        acc.w = fmaf(v.w, wt, acc.w);
    }

    float4 b = ((const float4*)bias)[lane];
    acc.x = fmaxf(acc.x + b.x, 0.f);
    acc.y = fmaxf(acc.y + b.y, 0.f);
    acc.z = fmaxf(acc.z + b.z, 0.f);
    acc.w = fmaxf(acc.w + b.w, 0.f);
    ((float4*)hout)[(size_t)node * 32 + lane] = acc;
}

// ---------------- mean pool (sorted batch: run-length + rare atomics) -------
#define NPB 128
__global__ void k_pool(const float* __restrict__ h, const void* batchp) {
    __shared__ int sg[NPB];
    int base = blockIdx.x * NPB;
    int t = threadIdx.x;
    int n_here = N_NODES - base;
    if (n_here > NPB) n_here = NPB;
    if (t < n_here) sg[t] = load_idx(batchp, base + t);
    __syncthreads();

    float acc = 0.f;
    int cur = sg[0];
    int runstart = 0;
    for (int n = 0; n < n_here; n++) {
        int g = sg[n];
        if (g != cur) {
            atomicAdd(&g_pool[cur * D + t], acc);
            if (t == 0) atomicAdd(&g_cnt[cur], n - runstart);
            acc = 0.f; cur = g; runstart = n;
        }
        acc += h[(size_t)(base + n) * D + t];
    }
    atomicAdd(&g_pool[cur * D + t], acc);
    if (t == 0) atomicAdd(&g_cnt[cur], n_here - runstart);
}

// ---------------- final FC: out = relu( (pool/cnt) @ Wfc + bfc ) ------------
__global__ void k_fc(const float* __restrict__ Wfc,
                     const float* __restrict__ bfc,
                     float* __restrict__ out) {
    __shared__ float srow[D];
    int g = blockIdx.x;
    int t = threadIdx.x;
    float cnt = fmaxf((float)g_cnt[g], 1.0f);
    srow[t] = g_pool[g * D + t] / cnt;
    __syncthreads();
    float acc = bfc[t];
    #pragma unroll 4
    for (int k = 0; k < D; k++)
        acc = fmaf(srow[k], Wfc[k * D + t], acc);
    out[g * D + t] = fmaxf(acc, 0.f);
}

// ---------------- launch ----------------------------------------------------
extern "C" void kernel_launch(void* const* d_in, const int* in_sizes, int n_in,
                              void* d_out, int out_size) {
    const float* x    = (const float*)d_in[0];
    const void*  edge = d_in[1];
    const void*  batch= d_in[2];
    const float* W1   = (const float*)d_in[3];
    const float* b1   = (const float*)d_in[4];
    const float* W2   = (const float*)d_in[5];
    const float* b2   = (const float*)d_in[6];
    const float* Wfc  = (const float*)d_in[7];
    const float* bfc  = (const float*)d_in[8];
    float* out = (float*)d_out;

    void *ph1, *ph2, *pwt;
    cudaGetSymbolAddress(&ph1, g_h1);
    cudaGetSymbolAddress(&ph2, g_h2);
    cudaGetSymbolAddress(&pwt, g_WT);
    float* h1 = (float*)ph1;
    float* h2 = (float*)ph2;
    float* wt = (float*)pwt;

    cudaFuncSetAttribute(k_gemm_mma, cudaFuncAttributeMaxDynamicSharedMemorySize,
                         GEMM_SMEM);

    const int EB = (N_EDGES + 255) / 256;
    const int NBlk = (N_NODES + 255) / 256;
    const int AGG_BLOCKS = (N_NODES * 32 + 255) / 256;
    const int GEMM_GRID = (N_NODES + 63) / 64;

    // ---- preprocessing ----
    k_init<<<NBlk, 256>>>(edge, W1, W2);
    k_deg<<<EB, 256>>>(edge);
    k_scan1<<<NB, SCAN_T>>>();
    k_scan3<<<NB, SCAN_T>>>();
    k_scatter<<<EB, 256>>>(edge);

    // ---- layer 1 ----
    k_gemm_mma<<<GEMM_GRID, 256, GEMM_SMEM>>>(x, wt, h1, N_NODES);
    k_agg<<<AGG_BLOCKS, 256>>>(h1, h2, b1);

    // ---- layer 2 ----
    k_gemm_mma<<<GEMM_GRID, 256, GEMM_SMEM>>>(h2, wt + D * D, h1, N_NODES);
    k_agg<<<AGG_BLOCKS, 256>>>(h1, h2, b2);

    // ---- pool + fc ----
    k_pool<<<(N_NODES + NPB - 1) / NPB, NPB>>>(h2, batch);
    k_fc<<<N_GRAPHS, D>>>(Wfc, bfc, out);
}

// round 4
// speedup vs baseline: 1.1697x; 1.0422x over previous
#include <cuda_runtime.h>
#include <cuda_bf16.h>
#include <cstdint>

#define N_NODES 100000
#define N_EDGES 1600000
#define N_GRAPHS 64
#define D 128

#define SCAN_T 1024
#define NB ((N_NODES + SCAN_T - 1) / SCAN_T)   // 98

// ---------------- scratch (device globals; no allocation allowed) ----------
__device__ float g_h1[(size_t)N_NODES * D];
__device__ float g_h2[(size_t)N_NODES * D];
__device__ int   g_deg[N_NODES];          // zero-init BSS; re-zeroed by k_pool
__device__ float g_dinv[N_NODES];
__device__ int   g_off[N_NODES + 1];
__device__ int   g_cur[N_NODES];
__device__ uint2 g_csr[N_EDGES];          // .x = src, .y = weight bits
__device__ int   g_bsum[NB];
__device__ float g_pool[N_GRAPHS * D];    // re-zeroed by k_agg
__device__ int   g_cnt[N_GRAPHS];
__device__ int   g_is64;
__device__ uint32_t g_Wh[2][D * 64];      // W^T bf16-hi, packed pairs [n][k/2]
__device__ uint32_t g_Wl[2][D * 64];      // W^T bf16-lo

// ---------------- helpers ---------------------------------------------------
__device__ __forceinline__ int load_idx(const void* p, long long i) {
    if (g_is64) return (int)((const long long*)p)[i];
    return ((const int*)p)[i];
}

__device__ __forceinline__ int detect64(const void* ep) {
    const int* p = (const int*)ep;
    int is64 = 1;
    #pragma unroll
    for (int j = 0; j < 8; j++)
        if (p[2 * j + 1] != 0) is64 = 0;
    return is64;
}

// split two fp32 into packed bf16x2 hi + bf16x2 lo (Markidis)
__device__ __forceinline__ void bfsplit2(float a, float b,
                                         uint32_t& h, uint32_t& l) {
    __nv_bfloat162 hv = __float22bfloat162_rn(make_float2(a, b));
    float2 hf = __bfloat1622float2(hv);
    __nv_bfloat162 lv = __float22bfloat162_rn(make_float2(a - hf.x, b - hf.y));
    h = *reinterpret_cast<uint32_t*>(&hv);
    l = *reinterpret_cast<uint32_t*>(&lv);
}

__device__ __forceinline__ void mma16(float* c, const uint32_t* a,
                                      const uint32_t* b) {
    asm volatile(
        "mma.sync.aligned.m16n8k16.row.col.f32.bf16.bf16.f32 "
        "{%0,%1,%2,%3}, {%4,%5,%6,%7}, {%8,%9}, {%0,%1,%2,%3};"
        : "+f"(c[0]), "+f"(c[1]), "+f"(c[2]), "+f"(c[3])
        : "r"(a[0]), "r"(a[1]), "r"(a[2]), "r"(a[3]), "r"(b[0]), "r"(b[1]));
}

// ---------------- deg count + init (W split/transpose, dtype, off[N]) -------
__global__ void k_deg(const void* ep, const float* W1, const float* W2) {
    int i = blockIdx.x * blockDim.x + threadIdx.x;
    if (i == 0) {
        g_is64 = detect64(ep);
        g_off[N_NODES] = N_EDGES;
    }
    if (i < 2 * D * 64) {          // one u32-pair of W^T per thread
        int m = i >> 13;           // 0 -> W1, 1 -> W2
        int j = i & 8191;
        int n = j >> 6, kp = j & 63;
        const float* W = m ? W2 : W1;
        float a = W[(2 * kp) * D + n];       // W^T[n][2kp]
        float b = W[(2 * kp + 1) * D + n];
        uint32_t h, l;
        bfsplit2(a, b, h, l);
        g_Wh[m][n * 64 + kp] = h;
        g_Wl[m][n * 64 + kp] = l;
    }
    if (i < N_EDGES) {
        int is64 = detect64(ep);
        int d = is64 ? (int)((const long long*)ep)[(long long)N_EDGES + i]
                     : ((const int*)ep)[N_EDGES + i];
        atomicAdd(&g_deg[d], 1);
    }
}

// ---------------- block-local exclusive scan + dinv --------------------------
__global__ void k_scan1() {
    __shared__ int s[SCAN_T];
    int i = blockIdx.x * SCAN_T + threadIdx.x;
    int v = (i < N_NODES) ? g_deg[i] : 0;
    if (i < N_NODES) g_dinv[i] = rsqrtf((float)v + 1.0f);  // +1 self loop
    s[threadIdx.x] = v;
    __syncthreads();
    #pragma unroll
    for (int off = 1; off < SCAN_T; off <<= 1) {
        int t = (threadIdx.x >= off) ? s[threadIdx.x - off] : 0;
        __syncthreads();
        s[threadIdx.x] += t;
        __syncthreads();
    }
    if (i < N_NODES) g_off[i] = s[threadIdx.x] - v;
    if (threadIdx.x == SCAN_T - 1) g_bsum[blockIdx.x] = s[SCAN_T - 1];
}

// ---------------- apply block offsets ----------------------------------------
__global__ void k_scan3() {
    __shared__ int s_boff;
    int b = blockIdx.x;
    int t = threadIdx.x;
    if (t == 0) s_boff = 0;
    __syncthreads();
    int partial = 0;
    for (int j = t; j < b; j += SCAN_T) partial += g_bsum[j];
    if (partial) atomicAdd(&s_boff, partial);
    __syncthreads();
    int i = b * SCAN_T + t;
    if (i < N_NODES) {
        int v = g_off[i] + s_boff;
        g_off[i] = v;
        g_cur[i] = v;
    }
}

// ---------------- CSR scatter (counting sort by dst, packed 8B entries) -----
__global__ void k_scatter(const void* ep) {
    int e = blockIdx.x * blockDim.x + threadIdx.x;
    if (e >= N_EDGES) return;
    int s = load_idx(ep, e);
    int d = load_idx(ep, (long long)N_EDGES + e);
    int pos = atomicAdd(&g_cur[d], 1);
    float w = g_dinv[s] * g_dinv[d];
    g_csr[pos] = make_uint2((uint32_t)s, __float_as_uint(w));
}

// ---------------- GEMM via mma.sync bf16 (3-term compensated) ---------------
// Y[n,128] = X[n,128] @ W. CTA: 256 thr, 64 rows x 128 cols.
// Warp: 32x32 = 2 m-frags x 4 n-frags of m16n8k16.
// Smem (bf16, stride 136 -> conflict-free u32 fragment loads):
//   sAh/sAl [64][136], sWh/sWl [128][136]
#define KS 136
#define GEMM_SMEM ((64 * KS * 2 + 128 * KS * 2) * 2)   // 104448 B

__global__ void __launch_bounds__(256) k_gemm(const float* __restrict__ X,
                                              const uint32_t* __restrict__ Wh,
                                              const uint32_t* __restrict__ Wl,
                                              float* __restrict__ Y,
                                              int nrows) {
    extern __shared__ __nv_bfloat16 sm[];
    __nv_bfloat16* sAh = sm;                    // [64][136]
    __nv_bfloat16* sAl = sAh + 64 * KS;
    __nv_bfloat16* sWh = sAl + 64 * KS;         // [128][136]
    __nv_bfloat16* sWl = sWh + 128 * KS;

    const int tid = threadIdx.x;
    const int rowBase = blockIdx.x * 64;

    // ---- stage A: load X fp32, split to bf16 hi/lo ----
    const float4* X4 = (const float4*)X;
    #pragma unroll
    for (int i = tid; i < 64 * 32; i += 256) {
        int r = i >> 5, c4 = i & 31;
        float4 v = make_float4(0.f, 0.f, 0.f, 0.f);
        if (rowBase + r < nrows) v = X4[(size_t)(rowBase + r) * 32 + c4];
        uint32_t h01, l01, h23, l23;
        bfsplit2(v.x, v.y, h01, l01);
        bfsplit2(v.z, v.w, h23, l23);
        *(uint2*)&sAh[r * KS + c4 * 4] = make_uint2(h01, h23);
        *(uint2*)&sAl[r * KS + c4 * 4] = make_uint2(l01, l23);
    }
    // ---- stage W: copy pre-split W^T into padded smem ----
    const uint4* Wh4 = (const uint4*)Wh;
    const uint4* Wl4 = (const uint4*)Wl;
    uint32_t* sWh32 = (uint32_t*)sWh;
    uint32_t* sWl32 = (uint32_t*)sWl;
    #pragma unroll
    for (int i = tid; i < 128 * 16; i += 256) {
        int n = i >> 4, kq = i & 15;
        *(uint4*)&sWh32[n * (KS / 2) + kq * 4] = Wh4[i];
        *(uint4*)&sWl32[n * (KS / 2) + kq * 4] = Wl4[i];
    }
    __syncthreads();

    const int wid = tid >> 5, lane = tid & 31;
    const int g = lane >> 2, tg = lane & 3;
    const int mbase = (wid >> 2) * 32;   // 0 or 32
    const int nbase = (wid & 3) * 32;    // 0,32,64,96

    float acc[2][4][4];
    #pragma unroll
    for (int mf = 0; mf < 2; mf++)
        #pragma unroll
        for (int nf = 0; nf < 4; nf++)
            #pragma unroll
            for (int j = 0; j < 4; j++) acc[mf][nf][j] = 0.f;

    #pragma unroll 2
    for (int kc = 0; kc < 8; kc++) {
        const int kA = kc * 16 + 2 * tg;

        uint32_t ah[2][4], al[2][4];
        #pragma unroll
        for (int mf = 0; mf < 2; mf++) {
            int r = mbase + mf * 16 + g;
            ah[mf][0] = *(uint32_t*)&sAh[r * KS + kA];
            ah[mf][1] = *(uint32_t*)&sAh[(r + 8) * KS + kA];
            ah[mf][2] = *(uint32_t*)&sAh[r * KS + kA + 8];
            ah[mf][3] = *(uint32_t*)&sAh[(r + 8) * KS + kA + 8];
            al[mf][0] = *(uint32_t*)&sAl[r * KS + kA];
            al[mf][1] = *(uint32_t*)&sAl[(r + 8) * KS + kA];
            al[mf][2] = *(uint32_t*)&sAl[r * KS + kA + 8];
            al[mf][3] = *(uint32_t*)&sAl[(r + 8) * KS + kA + 8];
        }
        uint32_t bh[4][2], bl[4][2];
        #pragma unroll
        for (int nf = 0; nf < 4; nf++) {
            int n = nbase + nf * 8 + g;
            bh[nf][0] = *(uint32_t*)&sWh[n * KS + kA];
            bh[nf][1] = *(uint32_t*)&sWh[n * KS + kA + 8];
            bl[nf][0] = *(uint32_t*)&sWl[n * KS + kA];
            bl[nf][1] = *(uint32_t*)&sWl[n * KS + kA + 8];
        }
        #pragma unroll
        for (int mf = 0; mf < 2; mf++)
            #pragma unroll
            for (int nf = 0; nf < 4; nf++) {
                mma16(acc[mf][nf], ah[mf], bh[nf]);
                mma16(acc[mf][nf], ah[mf], bl[nf]);
                mma16(acc[mf][nf], al[mf], bh[nf]);
            }
    }

    #pragma unroll
    for (int mf = 0; mf < 2; mf++) {
        int row = rowBase + mbase + mf * 16 + g;
        #pragma unroll
        for (int nf = 0; nf < 4; nf++) {
            int col = nbase + nf * 8 + 2 * tg;
            if (row < nrows)
                *(float2*)&Y[(size_t)row * D + col] =
                    make_float2(acc[mf][nf][0], acc[mf][nf][1]);
            if (row + 8 < nrows)
                *(float2*)&Y[(size_t)(row + 8) * D + col] =
                    make_float2(acc[mf][nf][2], acc[mf][nf][3]);
        }
    }
}

// ---------------- aggregation: out = relu( Ahat @ hin + bias ) --------------
// also zeroes g_pool/g_cnt for the pool stage (idempotent across both calls)
__global__ void k_agg(const float* __restrict__ hin,
                      float* __restrict__ hout,
                      const float* __restrict__ bias) {
    int gtid = blockIdx.x * blockDim.x + threadIdx.x;
    if (gtid < N_GRAPHS * D) g_pool[gtid] = 0.0f;
    if (gtid < N_GRAPHS) g_cnt[gtid] = 0;

    int node = gtid >> 5;
    if (node >= N_NODES) return;
    int lane = threadIdx.x & 31;

    const float4* h4 = (const float4*)hin;
    float dii = g_dinv[node];
    float sw = dii * dii;
    float4 a = h4[(size_t)node * 32 + lane];
    float4 acc = make_float4(a.x * sw, a.y * sw, a.z * sw, a.w * sw);

    int beg = g_off[node];
    int end = g_off[node + 1];
    for (int e = beg; e < end; e++) {
        uint2 sw2 = g_csr[e];
        float wt = __uint_as_float(sw2.y);
        float4 v = h4[(size_t)sw2.x * 32 + lane];
        acc.x = fmaf(v.x, wt, acc.x);
        acc.y = fmaf(v.y, wt, acc.y);
        acc.z = fmaf(v.z, wt, acc.z);
        acc.w = fmaf(v.w, wt, acc.w);
    }

    float4 b = ((const float4*)bias)[lane];
    acc.x = fmaxf(acc.x + b.x, 0.f);
    acc.y = fmaxf(acc.y + b.y, 0.f);
    acc.z = fmaxf(acc.z + b.z, 0.f);
    acc.w = fmaxf(acc.w + b.w, 0.f);
    ((float4*)hout)[(size_t)node * 32 + lane] = acc;
}

// ---------------- mean pool (sorted batch) + deg re-zero for next replay ----
#define NPB 128
__global__ void k_pool(const float* __restrict__ h, const void* batchp) {
    __shared__ int sg[NPB];
    int base = blockIdx.x * NPB;
    int t = threadIdx.x;
    if (base + t < N_NODES) g_deg[base + t] = 0;   // prep next replay
    int n_here = N_NODES - base;
    if (n_here > NPB) n_here = NPB;
    if (t < n_here) sg[t] = load_idx(batchp, base + t);
    __syncthreads();

    float acc = 0.f;
    int cur = sg[0];
    int runstart = 0;
    for (int n = 0; n < n_here; n++) {
        int g = sg[n];
        if (g != cur) {
            atomicAdd(&g_pool[cur * D + t], acc);
            if (t == 0) atomicAdd(&g_cnt[cur], n - runstart);
            acc = 0.f; cur = g; runstart = n;
        }
        acc += h[(size_t)(base + n) * D + t];
    }
    atomicAdd(&g_pool[cur * D + t], acc);
    if (t == 0) atomicAdd(&g_cnt[cur], n_here - runstart);
}

// ---------------- final FC: out = relu( (pool/cnt) @ Wfc + bfc ) ------------
__global__ void k_fc(const float* __restrict__ Wfc,
                     const float* __restrict__ bfc,
                     float* __restrict__ out) {
    __shared__ float srow[D];
    int g = blockIdx.x;
    int t = threadIdx.x;
    float cnt = fmaxf((float)g_cnt[g], 1.0f);
    srow[t] = g_pool[g * D + t] / cnt;
    __syncthreads();
    float acc = bfc[t];
    #pragma unroll 4
    for (int k = 0; k < D; k++)
        acc = fmaf(srow[k], Wfc[k * D + t], acc);
    out[g * D + t] = fmaxf(acc, 0.f);
}

// ---------------- launch ----------------------------------------------------
extern "C" void kernel_launch(void* const* d_in, const int* in_sizes, int n_in,
                              void* d_out, int out_size) {
    const float* x    = (const float*)d_in[0];
    const void*  edge = d_in[1];
    const void*  batch= d_in[2];
    const float* W1   = (const float*)d_in[3];
    const float* b1   = (const float*)d_in[4];
    const float* W2   = (const float*)d_in[5];
    const float* b2   = (const float*)d_in[6];
    const float* Wfc  = (const float*)d_in[7];
    const float* bfc  = (const float*)d_in[8];
    float* out = (float*)d_out;

    void *ph1, *ph2, *pwh, *pwl;
    cudaGetSymbolAddress(&ph1, g_h1);
    cudaGetSymbolAddress(&ph2, g_h2);
    cudaGetSymbolAddress(&pwh, g_Wh);
    cudaGetSymbolAddress(&pwl, g_Wl);
    float* h1 = (float*)ph1;
    float* h2 = (float*)ph2;
    uint32_t* wh = (uint32_t*)pwh;
    uint32_t* wl = (uint32_t*)pwl;

    cudaFuncSetAttribute(k_gemm, cudaFuncAttributeMaxDynamicSharedMemorySize,
                         GEMM_SMEM);

    const int EB = (N_EDGES + 255) / 256;
    const int AGG_BLOCKS = (N_NODES * 32 + 255) / 256;
    const int GEMM_GRID = (N_NODES + 63) / 64;

    // ---- preprocessing ----
    k_deg<<<EB, 256>>>(edge, W1, W2);
    k_scan1<<<NB, SCAN_T>>>();
    k_scan3<<<NB, SCAN_T>>>();
    k_scatter<<<EB, 256>>>(edge);

    // ---- layer 1 ----
    k_gemm<<<GEMM_GRID, 256, GEMM_SMEM>>>(x, wh, wl, h1, N_NODES);
    k_agg<<<AGG_BLOCKS, 256>>>(h1, h2, b1);

    // ---- layer 2 ----
    k_gemm<<<GEMM_GRID, 256, GEMM_SMEM>>>(h2, wh + D * 64, wl + D * 64, h1, N_NODES);
    k_agg<<<AGG_BLOCKS, 256>>>(h1, h2, b2);

    // ---- pool + fc ----
    k_pool<<<(N_NODES + NPB - 1) / NPB, NPB>>>(h2, batch);
    k_fc<<<N_GRAPHS, D>>>(Wfc, bfc, out);
}